// round 16
// baseline (speedup 1.0000x reference)
#include <cuda_runtime.h>
#include <cstdint>

#define BB 16
#define SS 2048
#define DD 512
#define NST 4                       // cp.async pipeline stages
#define ROWSTR 16                   // smem row stride floats (x4-perm conflict-free LDS.128)
#define ASTG_F (64 * ROWSTR)        // A stage floats (64 rows) = 1024 (4KB)
#define BSTG_F (128 * ROWSTR)       // B stage floats (128 n-rows) = 2048 (8KB)

// ---------------- device scratch ----------------
__device__ float g_a[BB * SS];
__device__ float g_c[BB * SS];
__device__ int   g_segstart[BB * (SS + 1)];
__device__ int   g_nwords[BB];
__device__ float g_mean[(size_t)BB * SS * DD];   // tf32-rounded, x4-k-permuted means
__device__ float g_wcT[DD * DD];                 // w_comb^T [N][K], tf32-rounded, permuted

__device__ __forceinline__ uint32_t f2tf32(float v) {
    uint32_t r;
    asm("cvt.rna.tf32.f32 %0, %1;" : "=r"(r) : "f"(v));
    return r;
}
__device__ __forceinline__ uint32_t smem_u32(const void* p) {
    uint32_t a;
    asm("{ .reg .u64 t; cvta.to.shared.u64 t, %1; cvt.u32.u64 %0, t; }" : "=r"(a) : "l"(p));
    return a;
}
#define CP16(dst, src) \
    asm volatile("cp.async.cg.shared.global [%0], [%1], 16;" :: "r"(dst), "l"(src))
#define CP_COMMIT() asm volatile("cp.async.commit_group;" ::: "memory")
#define CP_WAIT2()  asm volatile("cp.async.wait_group 2;" ::: "memory")

__device__ __forceinline__ void mma_tf32(float c[4], uint32_t a0, uint32_t a1,
                                         uint32_t a2, uint32_t a3,
                                         uint32_t b0, uint32_t b1) {
    asm volatile(
        "mma.sync.aligned.m16n8k8.row.col.f32.tf32.tf32.f32 "
        "{%0,%1,%2,%3}, {%4,%5,%6,%7}, {%8,%9}, {%0,%1,%2,%3};"
        : "+f"(c[0]), "+f"(c[1]), "+f"(c[2]), "+f"(c[3])
        : "r"(a0), "r"(a1), "r"(a2), "r"(a3), "r"(b0), "r"(b1));
}

// ---------------- K1: fused weight-transpose + per-frame score dots ----------------
__global__ void k_prep(const float* __restrict__ frame, const float* __restrict__ wscore,
                       const float* __restrict__ wc) {
    int bx = blockIdx.x;
    if (bx < 256) {
        __shared__ float t[32][33];
        int n0 = (bx & 15) * 32, k0 = (bx >> 4) * 32;
        int x = threadIdx.x & 31, y0 = threadIdx.x >> 5;   // 32 x 8
#pragma unroll
        for (int dy = 0; dy < 32; dy += 8)
            t[y0 + dy][x] = wc[(size_t)(k0 + y0 + dy) * DD + n0 + x];
        __syncthreads();
#pragma unroll
        for (int dy = 0; dy < 32; dy += 8) {
            int k = k0 + x;
            int kp = (k & ~15) | (4 * (k & 3)) | ((k >> 2) & 3);
            g_wcT[(size_t)(n0 + y0 + dy) * DD + kp] =
                __uint_as_float(f2tf32(t[x][y0 + dy]));
        }
        return;
    }
    int warp = (bx - 256) * 8 + (threadIdx.x >> 5);
    int lane = threadIdx.x & 31;
    if (warp >= BB * SS / 2) return;
    int row = warp * 2;
    const float4* r0 = (const float4*)(frame + (size_t)row * DD);
    const float4* r1 = (const float4*)(frame + (size_t)(row + 1) * DD);
    const float4* w1 = (const float4*)wscore;
    const float4* w2 = (const float4*)(wscore + DD);
    float d1a = 0.f, d2a = 0.f, d1b = 0.f, d2b = 0.f;
#pragma unroll
    for (int k = 0; k < 4; k++) {
        int i = lane + k * 32;
        float4 f0 = r0[i];
        float4 f1 = r1[i];
        float4 a = w1[i];
        float4 b = w2[i];
        d1a += f0.x * a.x + f0.y * a.y + f0.z * a.z + f0.w * a.w;
        d2a += f0.x * b.x + f0.y * b.y + f0.z * b.z + f0.w * b.w;
        d1b += f1.x * a.x + f1.y * a.y + f1.z * a.z + f1.w * a.w;
        d2b += f1.x * b.x + f1.y * b.y + f1.z * b.z + f1.w * b.w;
    }
#pragma unroll
    for (int off = 16; off; off >>= 1) {
        d1a += __shfl_down_sync(0xFFFFFFFFu, d1a, off);
        d2a += __shfl_down_sync(0xFFFFFFFFu, d2a, off);
        d1b += __shfl_down_sync(0xFFFFFFFFu, d1b, off);
        d2b += __shfl_down_sync(0xFFFFFFFFu, d2b, off);
    }
    if (lane == 0) {
        g_a[row] = d1a;     g_c[row] = d2a;
        g_a[row + 1] = d1b; g_c[row + 1] = d2b;
    }
}

// ---------------- K2: per-batch segment scan ----------------
__global__ void k_scan(const float* __restrict__ bscore_p, float* __restrict__ out_tail) {
    int b   = blockIdx.x;
    int tid = threadIdx.x;
    float bs = *bscore_p;
    int t0 = tid * 2, t1 = t0 + 1;
    int s0 = (t0 == 0) ? 0
             : (((g_a[b * SS + t0 - 1] + g_c[b * SS + t0] + bs) > 0.5f) ? 0 : 1);
    int s1 = (((g_a[b * SS + t1 - 1] + g_c[b * SS + t1] + bs) > 0.5f) ? 0 : 1);

    __shared__ int sc[1024];
    sc[tid] = s0 + s1;
    __syncthreads();
    for (int off = 1; off < 1024; off <<= 1) {
        int v   = sc[tid];
        int add = (tid >= off) ? sc[tid - off] : 0;
        __syncthreads();
        sc[tid] = v + add;
        __syncthreads();
    }
    int excl = (tid == 0) ? 0 : sc[tid - 1];
    int seg0 = excl + s0;
    int seg1 = excl + s0 + s1;

    int base = b * (SS + 1);
    if (t0 == 0 || s0 == 1) g_segstart[base + seg0] = t0;
    if (s1 == 1)            g_segstart[base + seg1] = t1;
    if (t1 == SS - 1) {
        int nw = seg1 + 1;
        g_nwords[b] = nw;
        g_segstart[base + nw] = SS;
        if (out_tail) out_tail[b] = (float)nw;
    }
}

// ---------------- K3: segment means (tf32, x4-k-permuted), 8 words/block ----------
__global__ void k_mean(const float* __restrict__ frame) {
    int j = blockIdx.x * 8 + (threadIdx.x >> 5);   // word index
    int lane = threadIdx.x & 31;
    int b = j / SS, w = j % SS;
    if (w >= g_nwords[b]) return;
    int base = b * (SS + 1);
    int st = g_segstart[base + w];
    int en = g_segstart[base + w + 1];
    float inv = 1.0f / (float)(en - st);
    float a[16];
#pragma unroll
    for (int i = 0; i < 16; i++) a[i] = 0.f;
    for (int t = st; t < en; t++) {
        const float4* p = (const float4*)(frame + ((size_t)(b * SS + t)) * DD + lane * 16);
#pragma unroll
        for (int q = 0; q < 4; q++) {
            float4 v = p[q];
            a[q * 4 + 0] += v.x; a[q * 4 + 1] += v.y;
            a[q * 4 + 2] += v.z; a[q * 4 + 3] += v.w;
        }
    }
    uint4* dst = (uint4*)(g_mean + (size_t)j * DD + lane * 16);
#pragma unroll
    for (int q = 0; q < 4; q++) {
        uint4 o;
        o.x = f2tf32(a[q] * inv);
        o.y = f2tf32(a[q + 4] * inv);
        o.z = f2tf32(a[q + 8] * inv);
        o.w = f2tf32(a[q + 12] * inv);
        dst[q] = o;
    }
}

// ---------------- K4: tf32 mma.sync GEMM, CTA 64x128, warp tile 16x64, 3 CTAs/SM --
__global__ void __launch_bounds__(256, 3)
k_gemm_tc(const float* __restrict__ bc, float* __restrict__ out) {
    int b    = blockIdx.z;
    int row0 = blockIdx.y * 64;
    int col0 = blockIdx.x * 128;
    int nw   = g_nwords[b];
    int tid  = threadIdx.x;
    float* outbase = out + (size_t)b * SS * DD;

    if (row0 >= nw) {
        float4 z = make_float4(0.f, 0.f, 0.f, 0.f);
        for (int i = tid; i < 64 * 32; i += 256) {
            int r = i >> 5, cq = i & 31;
            ((float4*)(outbase + (size_t)(row0 + r) * DD + col0))[cq] = z;
        }
        return;
    }

    extern __shared__ float sm[];
    float* AsB = sm;                          // NST * ASTG_F
    float* BsB = sm + NST * ASTG_F;           // NST * BSTG_F

    const float* A  = g_mean + ((size_t)b * SS + row0) * DD;
    const float* Bm = g_wcT + (size_t)col0 * DD;

    uint32_t aA = smem_u32(AsB), aB = smem_u32(BsB);
    // A: 64 rows x 4 chunks = 256 chunks, 1/thread. B: 128 x 4 = 512 chunks, 2/thread.
    int rA  = tid >> 2, cA = tid & 3;
    uint32_t dA = (uint32_t)rA * 64 + (uint32_t)cA * 16;
    int rB0 = tid >> 2, cB0 = tid & 3;
    int rB1 = (tid + 256) >> 2, cB1 = (tid + 256) & 3;
    uint32_t dB0 = (uint32_t)rB0 * 64 + (uint32_t)cB0 * 16;
    uint32_t dB1 = (uint32_t)rB1 * 64 + (uint32_t)cB1 * 16;

    int wid  = tid >> 5;
    int lane = tid & 31;
    int wm   = wid >> 1;                      // warp row (x16), 0..3
    int wn   = wid & 1;                       // warp col (x64), 0..1
    int gid  = lane >> 2;
    int tq   = lane & 3;

    float acc[8][4];
#pragma unroll
    for (int nt = 0; nt < 8; nt++)
#pragma unroll
        for (int i = 0; i < 4; i++) acc[nt][i] = 0.f;

    // prologue: stages 0..2
#pragma unroll
    for (int p = 0; p < 3; p++) {
        CP16(aA + p * (ASTG_F * 4) + dA, A + (size_t)rA * DD + p * 16 + cA * 4);
        uint32_t sb = p * (BSTG_F * 4);
        CP16(aB + sb + dB0, Bm + (size_t)rB0 * DD + p * 16 + cB0 * 4);
        CP16(aB + sb + dB1, Bm + (size_t)rB1 * DD + p * 16 + cB1 * 4);
        CP_COMMIT();
    }

    const int NKT = DD / 16;                  // 32
    for (int kt = 0; kt < NKT; kt++) {
        CP_WAIT2();
        __syncthreads();

        if (kt + 3 < NKT) {
            int p = kt + 3;
            CP16(aA + (uint32_t)(p & 3) * (ASTG_F * 4) + dA,
                 A + (size_t)rA * DD + p * 16 + cA * 4);
            uint32_t sb = (uint32_t)(p & 3) * (BSTG_F * 4);
            CP16(aB + sb + dB0, Bm + (size_t)rB0 * DD + p * 16 + cB0 * 4);
            CP16(aB + sb + dB1, Bm + (size_t)rB1 * DD + p * 16 + cB1 * 4);
        }
        CP_COMMIT();

        const float* as = AsB + (kt & 3) * ASTG_F;
        const float* bs = BsB + (kt & 3) * BSTG_F;

        // A fragments: 2 x LDS.128 (16-row warp tile, both ks halves)
        int rb = wm * 16 + gid;
        float4 pa0 = *(const float4*)(as + rb * ROWSTR + 4 * tq);
        float4 pa1 = *(const float4*)(as + (rb + 8) * ROWSTR + 4 * tq);

        // B fragments in 2 groups of 4 nt (caps live registers)
#pragma unroll
        for (int bg = 0; bg < 2; bg++) {
            float4 pb[4];
#pragma unroll
            for (int jj = 0; jj < 4; jj++) {
                int nb = wn * 64 + (bg * 4 + jj) * 8 + gid;
                pb[jj] = *(const float4*)(bs + nb * ROWSTR + 4 * tq);
            }
#pragma unroll
            for (int jj = 0; jj < 4; jj++) {
                int nt = bg * 4 + jj;
                mma_tf32(acc[nt],
                         __float_as_uint(pa0.x), __float_as_uint(pa1.x),
                         __float_as_uint(pa0.y), __float_as_uint(pa1.y),
                         __float_as_uint(pb[jj].x), __float_as_uint(pb[jj].y));
                mma_tf32(acc[nt],
                         __float_as_uint(pa0.z), __float_as_uint(pa1.z),
                         __float_as_uint(pa0.w), __float_as_uint(pa1.w),
                         __float_as_uint(pb[jj].z), __float_as_uint(pb[jj].w));
            }
        }
    }

    // epilogue: bias + zero padded rows, direct stores
    int r0g = row0 + wm * 16 + gid;
    int r1g = r0g + 8;
#pragma unroll
    for (int nt = 0; nt < 8; nt++) {
        int col = col0 + wn * 64 + nt * 8 + 2 * tq;
        float2 bias = *(const float2*)(bc + col);
        float2 v0, v1;
        if (r0g < nw) {
            v0.x = acc[nt][0] + bias.x;
            v0.y = acc[nt][1] + bias.y;
        } else { v0.x = 0.f; v0.y = 0.f; }
        if (r1g < nw) {
            v1.x = acc[nt][2] + bias.x;
            v1.y = acc[nt][3] + bias.y;
        } else { v1.x = 0.f; v1.y = 0.f; }
        *(float2*)(outbase + (size_t)r0g * DD + col) = v0;
        *(float2*)(outbase + (size_t)r1g * DD + col) = v1;
    }
}

// ---------------- launcher ----------------
extern "C" void kernel_launch(void* const* d_in, const int* in_sizes, int n_in,
                              void* d_out, int out_size) {
    const float* frame  = (const float*)d_in[0];   // [B,S,D]
    const float* wscore = (const float*)d_in[1];   // [2D,1]
    const float* bscore = (const float*)d_in[2];   // [1]
    const float* wcomb  = (const float*)d_in[3];   // [D,D]
    const float* bcomb  = (const float*)d_in[4];   // [D]
    float* out = (float*)d_out;

    float* tail = (out_size >= BB * SS * DD + BB) ? out + (size_t)BB * SS * DD : nullptr;

    const int SMEM_DYN = NST * (ASTG_F + BSTG_F) * 4;   // 48 KB
    cudaFuncSetAttribute(k_gemm_tc, cudaFuncAttributeMaxDynamicSharedMemorySize, SMEM_DYN);

    k_prep<<<256 + (BB * SS) / 16, 256>>>(frame, wscore, wcomb);
    k_scan<<<BB, 1024>>>(bscore, tail);
    k_mean<<<(BB * SS) / 8, 256>>>(frame);
    dim3 grid(DD / 128, SS / 64, BB);
    k_gemm_tc<<<grid, 256, SMEM_DYN>>>(bcomb, out);
}

// round 17
// speedup vs baseline: 1.4282x; 1.4282x over previous
#include <cuda_runtime.h>
#include <cuda_fp16.h>
#include <cstdint>

#define BB 16
#define SS 2048
#define DD 512
#define NST 4                       // cp.async pipeline stages
#define ROWH 16                     // halves per row per 16-k stage (32B)
#define STAGE_H (128 * ROWH)        // halves per stage per operand (2048 = 4KB)

// ---------------- device scratch ----------------
__device__ float    g_a[BB * SS];
__device__ float    g_c[BB * SS];
__device__ int      g_segstart[BB * (SS + 1)];
__device__ int      g_nwords[BB];
__device__ uint16_t g_mean_h[(size_t)BB * SS * DD];  // fp16, k-pair-permuted means (32MB)
__device__ uint16_t g_wcT_h[DD * DD];                // w_comb^T [N][K] fp16, permuted

__device__ __forceinline__ uint32_t packh2(float lo, float hi) {
    __half2 h = __floats2half2_rn(lo, hi);   // low 16 bits <- lo, high <- hi
    return *(uint32_t*)&h;
}
__device__ __forceinline__ uint32_t smem_u32(const void* p) {
    uint32_t a;
    asm("{ .reg .u64 t; cvta.to.shared.u64 t, %1; cvt.u32.u64 %0, t; }" : "=r"(a) : "l"(p));
    return a;
}
#define CP16(dst, src) \
    asm volatile("cp.async.cg.shared.global [%0], [%1], 16;" :: "r"(dst), "l"(src))
#define CP_COMMIT() asm volatile("cp.async.commit_group;" ::: "memory")
#define CP_WAIT2()  asm volatile("cp.async.wait_group 2;" ::: "memory")

__device__ __forceinline__ void mma_f16(float c[4], uint32_t a0, uint32_t a1,
                                        uint32_t a2, uint32_t a3,
                                        uint32_t b0, uint32_t b1) {
    asm volatile(
        "mma.sync.aligned.m16n8k16.row.col.f32.f16.f16.f32 "
        "{%0,%1,%2,%3}, {%4,%5,%6,%7}, {%8,%9}, {%0,%1,%2,%3};"
        : "+f"(c[0]), "+f"(c[1]), "+f"(c[2]), "+f"(c[3])
        : "r"(a0), "r"(a1), "r"(a2), "r"(a3), "r"(b0), "r"(b1));
}

// ---------------- K1: fused weight-transpose(fp16) + per-frame score dots ---------
// perm within 16-k group: orig m -> new pos: m<8: 4*(m>>1)+(m&1); m>=8: 4*((m-8)>>1)+2+(m&1)
__global__ void k_prep(const float* __restrict__ frame, const float* __restrict__ wscore,
                       const float* __restrict__ wc) {
    int bx = blockIdx.x;
    if (bx < 256) {
        __shared__ float t[32][33];
        int n0 = (bx & 15) * 32, k0 = (bx >> 4) * 32;
        int x = threadIdx.x & 31, y0 = threadIdx.x >> 5;   // 32 x 8
#pragma unroll
        for (int dy = 0; dy < 32; dy += 8)
            t[y0 + dy][x] = wc[(size_t)(k0 + y0 + dy) * DD + n0 + x];
        __syncthreads();
#pragma unroll
        for (int dy = 0; dy < 32; dy += 8) {
            int k = k0 + x;
            int m = k & 15;
            int kp = (k & ~15) | (((m >> 1) & 3) << 2) | ((m >> 3) << 1) | (m & 1);
            g_wcT_h[(size_t)(n0 + y0 + dy) * DD + kp] =
                __half_as_ushort(__float2half_rn(t[x][y0 + dy]));
        }
        return;
    }
    int warp = (bx - 256) * 8 + (threadIdx.x >> 5);
    int lane = threadIdx.x & 31;
    if (warp >= BB * SS / 2) return;
    int row = warp * 2;
    const float4* r0 = (const float4*)(frame + (size_t)row * DD);
    const float4* r1 = (const float4*)(frame + (size_t)(row + 1) * DD);
    const float4* w1 = (const float4*)wscore;
    const float4* w2 = (const float4*)(wscore + DD);
    float d1a = 0.f, d2a = 0.f, d1b = 0.f, d2b = 0.f;
#pragma unroll
    for (int k = 0; k < 4; k++) {
        int i = lane + k * 32;
        float4 f0 = r0[i];
        float4 f1 = r1[i];
        float4 a = w1[i];
        float4 b = w2[i];
        d1a += f0.x * a.x + f0.y * a.y + f0.z * a.z + f0.w * a.w;
        d2a += f0.x * b.x + f0.y * b.y + f0.z * b.z + f0.w * b.w;
        d1b += f1.x * a.x + f1.y * a.y + f1.z * a.z + f1.w * a.w;
        d2b += f1.x * b.x + f1.y * b.y + f1.z * b.z + f1.w * b.w;
    }
#pragma unroll
    for (int off = 16; off; off >>= 1) {
        d1a += __shfl_down_sync(0xFFFFFFFFu, d1a, off);
        d2a += __shfl_down_sync(0xFFFFFFFFu, d2a, off);
        d1b += __shfl_down_sync(0xFFFFFFFFu, d1b, off);
        d2b += __shfl_down_sync(0xFFFFFFFFu, d2b, off);
    }
    if (lane == 0) {
        g_a[row] = d1a;     g_c[row] = d2a;
        g_a[row + 1] = d1b; g_c[row + 1] = d2b;
    }
}

// ---------------- K2: per-batch segment scan ----------------
__global__ void k_scan(const float* __restrict__ bscore_p, float* __restrict__ out_tail) {
    int b   = blockIdx.x;
    int tid = threadIdx.x;
    float bs = *bscore_p;
    int t0 = tid * 2, t1 = t0 + 1;
    int s0 = (t0 == 0) ? 0
             : (((g_a[b * SS + t0 - 1] + g_c[b * SS + t0] + bs) > 0.5f) ? 0 : 1);
    int s1 = (((g_a[b * SS + t1 - 1] + g_c[b * SS + t1] + bs) > 0.5f) ? 0 : 1);

    __shared__ int sc[1024];
    sc[tid] = s0 + s1;
    __syncthreads();
    for (int off = 1; off < 1024; off <<= 1) {
        int v   = sc[tid];
        int add = (tid >= off) ? sc[tid - off] : 0;
        __syncthreads();
        sc[tid] = v + add;
        __syncthreads();
    }
    int excl = (tid == 0) ? 0 : sc[tid - 1];
    int seg0 = excl + s0;
    int seg1 = excl + s0 + s1;

    int base = b * (SS + 1);
    if (t0 == 0 || s0 == 1) g_segstart[base + seg0] = t0;
    if (s1 == 1)            g_segstart[base + seg1] = t1;
    if (t1 == SS - 1) {
        int nw = seg1 + 1;
        g_nwords[b] = nw;
        g_segstart[base + nw] = SS;
        if (out_tail) out_tail[b] = (float)nw;
    }
}

// ---------------- K3: segment means -> fp16, pair-permuted, 8 words/block ---------
// new-pos u32 pairs: u0={k0,k1} u1={k8,k9} u2={k2,k3} u3={k10,k11}
//                    u4={k4,k5} u5={k12,k13} u6={k6,k7} u7={k14,k15}
__global__ void k_mean(const float* __restrict__ frame) {
    int j = blockIdx.x * 8 + (threadIdx.x >> 5);   // word index
    int lane = threadIdx.x & 31;
    int b = j / SS, w = j % SS;
    if (w >= g_nwords[b]) return;
    int base = b * (SS + 1);
    int st = g_segstart[base + w];
    int en = g_segstart[base + w + 1];
    float inv = 1.0f / (float)(en - st);
    float a[16];
#pragma unroll
    for (int i = 0; i < 16; i++) a[i] = 0.f;
    for (int t = st; t < en; t++) {
        const float4* p = (const float4*)(frame + ((size_t)(b * SS + t)) * DD + lane * 16);
#pragma unroll
        for (int q = 0; q < 4; q++) {
            float4 v = p[q];
            a[q * 4 + 0] += v.x; a[q * 4 + 1] += v.y;
            a[q * 4 + 2] += v.z; a[q * 4 + 3] += v.w;
        }
    }
    uint4 o0, o1;
    o0.x = packh2(a[0] * inv,  a[1] * inv);
    o0.y = packh2(a[8] * inv,  a[9] * inv);
    o0.z = packh2(a[2] * inv,  a[3] * inv);
    o0.w = packh2(a[10] * inv, a[11] * inv);
    o1.x = packh2(a[4] * inv,  a[5] * inv);
    o1.y = packh2(a[12] * inv, a[13] * inv);
    o1.z = packh2(a[6] * inv,  a[7] * inv);
    o1.w = packh2(a[14] * inv, a[15] * inv);
    uint4* dst = (uint4*)(g_mean_h + (size_t)j * DD + lane * 16);
    dst[0] = o0;
    dst[1] = o1;
}

// ---------------- K4: fp16 m16n8k16 mma.sync GEMM (R14 skeleton) ------------------
__global__ void __launch_bounds__(256, 2)
k_gemm_tc(const float* __restrict__ bc, float* __restrict__ out) {
    int b    = blockIdx.z;
    int row0 = blockIdx.y * 128;
    int col0 = blockIdx.x * 128;
    int nw   = g_nwords[b];
    int tid  = threadIdx.x;
    float* outbase = out + (size_t)b * SS * DD;

    if (row0 >= nw) {
        float4 z = make_float4(0.f, 0.f, 0.f, 0.f);
        for (int i = tid; i < 128 * 32; i += 256) {
            int r = i >> 5, cq = i & 31;
            ((float4*)(outbase + (size_t)(row0 + r) * DD + col0))[cq] = z;
        }
        return;
    }

    extern __shared__ uint16_t smh[];
    uint16_t* AsB = smh;                       // NST * STAGE_H halves
    uint16_t* BsB = smh + NST * STAGE_H;

    const uint16_t* A  = g_mean_h + ((size_t)b * SS + row0) * DD;
    const uint16_t* Bm = g_wcT_h + (size_t)col0 * DD;

    uint32_t aA = smem_u32(AsB), aB = smem_u32(BsB);
    // per stage per operand: 128 rows x 32B = 256 x 16B chunks; 1 A + 1 B chunk/thread
    int rC = tid >> 1, cC = tid & 1;
    uint32_t dC = (uint32_t)rC * 32 + (uint32_t)cC * 16;

    int wid  = tid >> 5;
    int lane = tid & 31;
    int wm   = wid & 3;                        // warp row (x32)
    int wn   = wid >> 2;                       // warp col (x64)
    int gid  = lane >> 2;
    int tq   = lane & 3;

    float acc[2][8][4];
#pragma unroll
    for (int mt = 0; mt < 2; mt++)
#pragma unroll
        for (int nt = 0; nt < 8; nt++)
#pragma unroll
            for (int i = 0; i < 4; i++) acc[mt][nt][i] = 0.f;

    // prologue: stages 0..2
#pragma unroll
    for (int p = 0; p < 3; p++) {
        uint32_t sb = p * (STAGE_H * 2);
        CP16(aA + sb + dC, A + (size_t)rC * DD + p * 16 + cC * 8);
        CP16(aB + sb + dC, Bm + (size_t)rC * DD + p * 16 + cC * 8);
        CP_COMMIT();
    }

    const int NKT = DD / 16;                   // 32
    for (int kt = 0; kt < NKT; kt++) {
        CP_WAIT2();
        __syncthreads();

        if (kt + 3 < NKT) {
            int p = kt + 3;
            uint32_t sb = (uint32_t)(p & 3) * (STAGE_H * 2);
            CP16(aA + sb + dC, A + (size_t)rC * DD + p * 16 + cC * 8);
            CP16(aB + sb + dC, Bm + (size_t)rC * DD + p * 16 + cC * 8);
        }
        CP_COMMIT();

        const uint16_t* as = AsB + (kt & 3) * STAGE_H;
        const uint16_t* bs = BsB + (kt & 3) * STAGE_H;

        // A fragments: LDS.64 x4 -> a0/a2 (row gid), a1/a3 (row gid+8) per mt
        uint2 pa0[2], pa1[2];
#pragma unroll
        for (int mt = 0; mt < 2; mt++) {
            int rb = wm * 32 + mt * 16 + gid;
            pa0[mt] = *(const uint2*)(as + rb * ROWH + 4 * tq);
            pa1[mt] = *(const uint2*)(as + (rb + 8) * ROWH + 4 * tq);
        }
        // B fragments in 2 groups of 4 nt
#pragma unroll
        for (int bg = 0; bg < 2; bg++) {
            uint2 pb[4];
#pragma unroll
            for (int jj = 0; jj < 4; jj++) {
                int nb = wn * 64 + (bg * 4 + jj) * 8 + gid;
                pb[jj] = *(const uint2*)(bs + nb * ROWH + 4 * tq);
            }
#pragma unroll
            for (int mt = 0; mt < 2; mt++)
#pragma unroll
                for (int jj = 0; jj < 4; jj++) {
                    int nt = bg * 4 + jj;
                    mma_f16(acc[mt][nt],
                            pa0[mt].x, pa1[mt].x, pa0[mt].y, pa1[mt].y,
                            pb[jj].x, pb[jj].y);
                }
        }
    }

    // epilogue: bias + zero padded rows, direct stores (c0,c1 -> cols 2tq,2tq+1)
#pragma unroll
    for (int mt = 0; mt < 2; mt++) {
        int r0g = row0 + wm * 32 + mt * 16 + gid;
        int r1g = r0g + 8;
#pragma unroll
        for (int nt = 0; nt < 8; nt++) {
            int col = col0 + wn * 64 + nt * 8 + 2 * tq;
            float2 bias = *(const float2*)(bc + col);
            float2 v0, v1;
            if (r0g < nw) {
                v0.x = acc[mt][nt][0] + bias.x;
                v0.y = acc[mt][nt][1] + bias.y;
            } else { v0.x = 0.f; v0.y = 0.f; }
            if (r1g < nw) {
                v1.x = acc[mt][nt][2] + bias.x;
                v1.y = acc[mt][nt][3] + bias.y;
            } else { v1.x = 0.f; v1.y = 0.f; }
            *(float2*)(outbase + (size_t)r0g * DD + col) = v0;
            *(float2*)(outbase + (size_t)r1g * DD + col) = v1;
        }
    }
}

// ---------------- launcher ----------------
extern "C" void kernel_launch(void* const* d_in, const int* in_sizes, int n_in,
                              void* d_out, int out_size) {
    const float* frame  = (const float*)d_in[0];   // [B,S,D]
    const float* wscore = (const float*)d_in[1];   // [2D,1]
    const float* bscore = (const float*)d_in[2];   // [1]
    const float* wcomb  = (const float*)d_in[3];   // [D,D]
    const float* bcomb  = (const float*)d_in[4];   // [D]
    float* out = (float*)d_out;

    float* tail = (out_size >= BB * SS * DD + BB) ? out + (size_t)BB * SS * DD : nullptr;

    const int SMEM_DYN = 2 * NST * STAGE_H * 2;    // 32 KB
    cudaFuncSetAttribute(k_gemm_tc, cudaFuncAttributeMaxDynamicSharedMemorySize, SMEM_DYN);

    k_prep<<<256 + (BB * SS) / 16, 256>>>(frame, wscore, wcomb);
    k_scan<<<BB, 1024>>>(bscore, tail);
    k_mean<<<(BB * SS) / 8, 256>>>(frame);
    dim3 grid(DD / 128, SS / 128, BB);
    k_gemm_tc<<<grid, 256, SMEM_DYN>>>(bcomb, out);
}